// round 3
// baseline (speedup 1.0000x reference)
#include <cuda_runtime.h>
#include <cstdint>

// Problem constants
#define NN 1024
#define SS 144
#define RR 96
#define KK 128
#define DD 768
#define AA 48              // ablated = S - R
#define RK (RR*KK)         // 12288
#define SPLITK 6
#define KSPLIT (RK/SPLITK) // 2048

// Scratch (device globals: allocation-free rule). Referenced ONLY from device
// code — passing a __device__ symbol as a host-side kernel arg yields the
// host shadow address (the Round-1 bug: gemm1 wrote to garbage, P-part = 0).
__device__ float g_coeffs[(size_t)NN * RK];        // 50.3 MB  (N, R*K)
__device__ float g_part[(size_t)SPLITK * NN * DD]; // 18.9 MB  split-K partials
__device__ float g_lamk[RK];                       // padded lambdas (R,K)
__device__ float g_lmb[RK];                        // lam * dot(mean_r, base_rk)
__device__ int   g_ridx[RR];
__device__ int   g_aidx[AA];

// ---------------------------------------------------------------------------
// prep1: index dtype detection (int64 vs int32), padded lambdas
// indices are sorted strictly increasing, so for an int32 array word[1] >= 1;
// for little-endian int64, word[1] == 0 (high word of element 0).
// ---------------------------------------------------------------------------
__global__ void prep1_k(const int* __restrict__ rraw, const int* __restrict__ araw,
                        const float* __restrict__ lambdas, const int* __restrict__ blen) {
    __shared__ int soff[RR];
    int t = threadIdx.x; // 128 threads
    bool r64 = (rraw[1] == 0);
    bool a64 = (araw[1] == 0);
    if (t < RR) g_ridx[t] = r64 ? rraw[2 * t] : rraw[t];
    if (t < AA) g_aidx[t] = a64 ? araw[2 * t] : araw[t];
    if (t == 0) {
        int acc = 0;
        for (int r = 0; r < RR; r++) { soff[r] = acc; acc += blen[r]; }
    }
    __syncthreads();
    for (int i = t; i < RK; i += 128) {
        int r = i >> 7, k = i & 127;
        int len = blen[r];
        g_lamk[i] = (k < len) ? lambdas[soff[r] + k] : 0.0f;
    }
}

// ---------------------------------------------------------------------------
// prep2: g_lmb[r,k] = lamk[r,k] * dot(means[r,:], bases[r,k,:])
// one warp per (r,k); 12288 warps = 1536 blocks x 256
// ---------------------------------------------------------------------------
__global__ void prep2_k(const float* __restrict__ bases, const float* __restrict__ means) {
    int gw = (blockIdx.x * blockDim.x + threadIdx.x) >> 5;
    int lane = threadIdx.x & 31;
    if (gw >= RK) return;
    int r = gw >> 7;
    const float4* b4 = (const float4*)(bases + (size_t)gw * DD);
    const float4* m4 = (const float4*)(means + (size_t)r * DD);
    float s = 0.f;
    #pragma unroll 3
    for (int j = lane; j < DD / 4; j += 32) {
        float4 bb = b4[j], mm = m4[j];
        s += bb.x * mm.x + bb.y * mm.y + bb.z * mm.z + bb.w * mm.w;
    }
    #pragma unroll
    for (int o = 16; o; o >>= 1) s += __shfl_xor_sync(0xffffffffu, s, o);
    if (lane == 0) g_lmb[gw] = g_lamk[gw] * s;
}

// ---------------------------------------------------------------------------
// ablate_k: out[n,d] = sum_a x[n, aidx[a], d]   (initializes d_out)
// ---------------------------------------------------------------------------
__global__ void ablate_k(const float* __restrict__ x, float* __restrict__ out) {
    __shared__ int sa[AA];
    if (threadIdx.x < AA) sa[threadIdx.x] = g_aidx[threadIdx.x];
    __syncthreads();
    int i = blockIdx.x * 256 + threadIdx.x;     // < 196608
    int n = i / (DD / 4), c = i % (DD / 4);
    const float4* x4 = (const float4*)x;
    float4 s = make_float4(0.f, 0.f, 0.f, 0.f);
    int base = n * SS;
    #pragma unroll 4
    for (int a = 0; a < AA; a++) {
        float4 v = x4[(size_t)(base + sa[a]) * (DD / 4) + c];
        s.x += v.x; s.y += v.y; s.z += v.z; s.w += v.w;
    }
    ((float4*)out)[i] = s;
}

// ---------------------------------------------------------------------------
// GEMM1: per r, C_r = X_r @ B_r^T  (1024x768 @ 768x128), fused lam/mean:
//   g_coeffs[n, r*128+k] = lamk[r,k]*dot(x[n,ri,:], b[r,k,:]) - lmb[r,k]
// 128x128 tile, BK=32, 256 threads, 8x8/thread via packed fma.rn.f32x2.
// ---------------------------------------------------------------------------
__global__ __launch_bounds__(256, 2)
void gemm1_k(const float* __restrict__ x, const float* __restrict__ bases) {
    __shared__ float Ast[32 * 132];
    __shared__ float Bst[32 * 132];
    __shared__ float s_lamk[KK];
    __shared__ float s_lmb[KK];

    const int r  = blockIdx.y;
    const int n0 = blockIdx.x << 7;
    const int tid = threadIdx.x;
    if (tid < KK) { s_lamk[tid] = g_lamk[(r << 7) + tid]; s_lmb[tid] = g_lmb[(r << 7) + tid]; }
    const int tx = tid & 15, ty = tid >> 4;
    const int lrow = tid >> 3, lc4 = tid & 7;

    const float* Ab = x + (size_t)(n0 * SS + g_ridx[r]) * DD + (size_t)lrow * (SS * DD) + (lc4 << 2);
    const float* Bb = bases + (size_t)r * (KK * DD) + (size_t)lrow * DD + (lc4 << 2);

    unsigned long long acc[8][4];
    #pragma unroll
    for (int i = 0; i < 8; i++)
        #pragma unroll
        for (int j = 0; j < 4; j++) acc[i][j] = 0ull;

    for (int d0 = 0; d0 < DD; d0 += 32) {
        __syncthreads();
        #pragma unroll
        for (int i = 0; i < 4; i++) {
            const int arow = lrow + (i << 5);
            float4 av = *(const float4*)(Ab + (size_t)(i << 5) * (SS * DD) + d0);
            float4 bv = *(const float4*)(Bb + (size_t)(i << 5) * DD + d0);
            const int c = lc4 << 2;
            Ast[(c + 0) * 132 + arow] = av.x; Ast[(c + 1) * 132 + arow] = av.y;
            Ast[(c + 2) * 132 + arow] = av.z; Ast[(c + 3) * 132 + arow] = av.w;
            Bst[(c + 0) * 132 + arow] = bv.x; Bst[(c + 1) * 132 + arow] = bv.y;
            Bst[(c + 2) * 132 + arow] = bv.z; Bst[(c + 3) * 132 + arow] = bv.w;
        }
        __syncthreads();
        #pragma unroll 8
        for (int dd = 0; dd < 32; dd++) {
            const float4 a0 = *(const float4*)&Ast[dd * 132 + (ty << 2)];
            const float4 a1 = *(const float4*)&Ast[dd * 132 + 64 + (ty << 2)];
            const float4 b0 = *(const float4*)&Bst[dd * 132 + (tx << 2)];
            const float4 b1 = *(const float4*)&Bst[dd * 132 + 64 + (tx << 2)];
            unsigned long long bp[4];
            asm("mov.b64 %0,{%1,%2};" : "=l"(bp[0]) : "f"(b0.x), "f"(b0.y));
            asm("mov.b64 %0,{%1,%2};" : "=l"(bp[1]) : "f"(b0.z), "f"(b0.w));
            asm("mov.b64 %0,{%1,%2};" : "=l"(bp[2]) : "f"(b1.x), "f"(b1.y));
            asm("mov.b64 %0,{%1,%2};" : "=l"(bp[3]) : "f"(b1.z), "f"(b1.w));
            const float av8[8] = {a0.x, a0.y, a0.z, a0.w, a1.x, a1.y, a1.z, a1.w};
            #pragma unroll
            for (int i = 0; i < 8; i++) {
                unsigned long long ad;
                asm("mov.b64 %0,{%1,%1};" : "=l"(ad) : "f"(av8[i]));
                #pragma unroll
                for (int jp = 0; jp < 4; jp++)
                    asm("fma.rn.f32x2 %0, %1, %2, %0;" : "+l"(acc[i][jp]) : "l"(ad), "l"(bp[jp]));
            }
        }
    }

    #pragma unroll
    for (int i = 0; i < 8; i++) {
        const int n = n0 + ((i >> 2) << 6) + (ty << 2) + (i & 3);
        float* crow = g_coeffs + (size_t)n * RK + (r << 7);
        #pragma unroll
        for (int h = 0; h < 2; h++) {
            const int k = (h << 6) + (tx << 2);
            float p0x, p0y, p1x, p1y;
            asm("mov.b64 {%0,%1}, %2;" : "=f"(p0x), "=f"(p0y) : "l"(acc[i][h * 2 + 0]));
            asm("mov.b64 {%0,%1}, %2;" : "=f"(p1x), "=f"(p1y) : "l"(acc[i][h * 2 + 1]));
            float4 v;
            v.x = s_lamk[k + 0] * p0x - s_lmb[k + 0];
            v.y = s_lamk[k + 1] * p0y - s_lmb[k + 1];
            v.z = s_lamk[k + 2] * p1x - s_lmb[k + 2];
            v.w = s_lamk[k + 3] * p1y - s_lmb[k + 3];
            *(float4*)(crow + k) = v;
        }
    }
}

// ---------------------------------------------------------------------------
// GEMM2: g_part[z] = coeffs(1024,12288)[:, z*2048:(z+1)*2048] @ invb chunk
// grid (8,6,SPLITK) = 288 blocks -> 2 resident blocks/SM. Deterministic
// split-K via partial buffers + reduce_k (no float atomics).
// ---------------------------------------------------------------------------
__global__ __launch_bounds__(256, 2)
void gemm2_k(const float* __restrict__ invb) {
    __shared__ float Ast[32 * 132];
    __shared__ float Bs[32 * 128];

    const int n0 = blockIdx.x << 7;
    const int d0 = blockIdx.y << 7;
    const int z  = blockIdx.z;
    const int tid = threadIdx.x;
    const int tx = tid & 15, ty = tid >> 4;
    const int lrow = tid >> 3, lc4 = tid & 7;
    const int brow0 = tid >> 5, bc4 = tid & 31;

    const float* Ab = g_coeffs + (size_t)(n0 + lrow) * RK + (lc4 << 2);

    unsigned long long acc[8][4];
    #pragma unroll
    for (int i = 0; i < 8; i++)
        #pragma unroll
        for (int j = 0; j < 4; j++) acc[i][j] = 0ull;

    const int kend = z * KSPLIT + KSPLIT;
    for (int k0 = z * KSPLIT; k0 < kend; k0 += 32) {
        __syncthreads();
        #pragma unroll
        for (int i = 0; i < 4; i++) {
            float4 av = *(const float4*)(Ab + (size_t)(i << 5) * RK + k0);
            const int arow = lrow + (i << 5);
            const int c = lc4 << 2;
            Ast[(c + 0) * 132 + arow] = av.x; Ast[(c + 1) * 132 + arow] = av.y;
            Ast[(c + 2) * 132 + arow] = av.z; Ast[(c + 3) * 132 + arow] = av.w;
            const int brow = brow0 + (i << 3);
            float4 bv = *(const float4*)(invb + (size_t)(k0 + brow) * DD + d0 + (bc4 << 2));
            *(float4*)&Bs[(brow << 7) + (bc4 << 2)] = bv;
        }
        __syncthreads();
        #pragma unroll 8
        for (int dd = 0; dd < 32; dd++) {
            const float4 a0 = *(const float4*)&Ast[dd * 132 + (ty << 2)];
            const float4 a1 = *(const float4*)&Ast[dd * 132 + 64 + (ty << 2)];
            const float4 b0 = *(const float4*)&Bs[(dd << 7) + (tx << 2)];
            const float4 b1 = *(const float4*)&Bs[(dd << 7) + 64 + (tx << 2)];
            unsigned long long bp[4];
            asm("mov.b64 %0,{%1,%2};" : "=l"(bp[0]) : "f"(b0.x), "f"(b0.y));
            asm("mov.b64 %0,{%1,%2};" : "=l"(bp[1]) : "f"(b0.z), "f"(b0.w));
            asm("mov.b64 %0,{%1,%2};" : "=l"(bp[2]) : "f"(b1.x), "f"(b1.y));
            asm("mov.b64 %0,{%1,%2};" : "=l"(bp[3]) : "f"(b1.z), "f"(b1.w));
            const float av8[8] = {a0.x, a0.y, a0.z, a0.w, a1.x, a1.y, a1.z, a1.w};
            #pragma unroll
            for (int i = 0; i < 8; i++) {
                unsigned long long ad;
                asm("mov.b64 %0,{%1,%1};" : "=l"(ad) : "f"(av8[i]));
                #pragma unroll
                for (int jp = 0; jp < 4; jp++)
                    asm("fma.rn.f32x2 %0, %1, %2, %0;" : "+l"(acc[i][jp]) : "l"(ad), "l"(bp[jp]));
            }
        }
    }

    float* P = g_part + (size_t)z * (NN * DD);
    #pragma unroll
    for (int i = 0; i < 8; i++) {
        const int n = n0 + ((i >> 2) << 6) + (ty << 2) + (i & 3);
        #pragma unroll
        for (int h = 0; h < 2; h++) {
            const int d = d0 + (h << 6) + (tx << 2);
            float p0x, p0y, p1x, p1y;
            asm("mov.b64 {%0,%1}, %2;" : "=f"(p0x), "=f"(p0y) : "l"(acc[i][h * 2 + 0]));
            asm("mov.b64 {%0,%1}, %2;" : "=f"(p1x), "=f"(p1y) : "l"(acc[i][h * 2 + 1]));
            float4 v = make_float4(p0x, p0y, p1x, p1y);
            *(float4*)(P + (size_t)n * DD + d) = v;
        }
    }
}

// ---------------------------------------------------------------------------
// reduce_k: out += sum_z part[z]   (out already holds the ablated sum)
// ---------------------------------------------------------------------------
__global__ void reduce_k(float* __restrict__ out) {
    int i = blockIdx.x * 256 + threadIdx.x; // < 196608 float4
    float4 s = ((const float4*)out)[i];
    const float4* p4 = (const float4*)g_part;
    #pragma unroll
    for (int zz = 0; zz < SPLITK; zz++) {
        float4 v = p4[(size_t)zz * (NN * DD / 4) + i];
        s.x += v.x; s.y += v.y; s.z += v.z; s.w += v.w;
    }
    ((float4*)out)[i] = s;
}

// ---------------------------------------------------------------------------
extern "C" void kernel_launch(void* const* d_in, const int* in_sizes, int n_in,
                              void* d_out, int out_size) {
    (void)in_sizes; (void)n_in; (void)out_size;
    const float* x       = (const float*)d_in[0];
    const float* lambdas = (const float*)d_in[1];
    const float* bases   = (const float*)d_in[2];
    const float* invb    = (const float*)d_in[3];
    const float* means   = (const float*)d_in[4];
    const int*   rraw    = (const int*)d_in[5];
    const int*   araw    = (const int*)d_in[6];
    const int*   blen    = (const int*)d_in[7];
    float* out = (float*)d_out;

    prep1_k<<<1, 128>>>(rraw, araw, lambdas, blen);
    prep2_k<<<1536, 256>>>(bases, means);
    ablate_k<<<768, 256>>>(x, out);
    gemm1_k<<<dim3(8, RR, 1), 256>>>(x, bases);
    gemm2_k<<<dim3(8, 6, SPLITK), 256>>>(invb);
    reduce_k<<<768, 256>>>(out);
}

// round 7
// speedup vs baseline: 1.2460x; 1.2460x over previous
#include <cuda_runtime.h>
#include <cuda_bf16.h>
#include <cstdint>

#define NN 1024
#define SS 144
#define RR 96
#define KK 128
#define DD 768
#define AA 48
#define RK (RR*KK)         // 12288
#define SPLITK 3
#define KSPLIT (RK/SPLITK) // 4096

#define KCH 64                 // K elems per chunk
#define TILE_B 16384           // 128 rows x 64 bf16 x 2B
#define STAGE_B (4*TILE_B)     // Ahi Alo Bhi Blo
#define SM_TILES 2048
#define SMEMSZ (SM_TILES + 2*STAGE_B)   // 133120
#define SM_LAM 64
#define SM_LMB 576

// ---- scratch (device globals; only referenced from device code) ----
__device__ unsigned g_chl[(size_t)NN * RK];          // coeffs packed bf16 hi/lo
__device__ unsigned g_ivt[(size_t)DD * RK];          // invb^T packed bf16 hi/lo
__device__ float    g_part[(size_t)SPLITK * NN * DD];// split-K partials
__device__ float    g_lamk[RK];
__device__ float    g_lmb[RK];
__device__ int      g_ridx[RR];
__device__ int      g_aidx[AA];

// ---- helpers ----
__device__ __forceinline__ uint32_t smem_u32(const void* p) {
    uint32_t a; asm("{ .reg .u64 t; cvta.to.shared.u64 t, %1; cvt.u32.u64 %0, t; }" : "=r"(a) : "l"(p));
    return a;
}
#define SWZ(o) ((o) ^ (((o) >> 3) & 0x70))

__device__ __forceinline__ void ldsm4(uint32_t* r, uint32_t addr) {
    asm volatile("ldmatrix.sync.aligned.m8n8.x4.shared.b16 {%0,%1,%2,%3}, [%4];"
        : "=r"(r[0]), "=r"(r[1]), "=r"(r[2]), "=r"(r[3]) : "r"(addr));
}
__device__ __forceinline__ void mma16816(float* c, const uint32_t* a, uint32_t b0, uint32_t b1) {
    asm volatile("mma.sync.aligned.m16n8k16.row.col.f32.bf16.bf16.f32 "
        "{%0,%1,%2,%3}, {%4,%5,%6,%7}, {%8,%9}, {%0,%1,%2,%3};"
        : "+f"(c[0]), "+f"(c[1]), "+f"(c[2]), "+f"(c[3])
        : "r"(a[0]), "r"(a[1]), "r"(a[2]), "r"(a[3]), "r"(b0), "r"(b1));
}

// fp32 pair -> packed bf16 hi + bf16 lo (x in low half, y in high half)
__device__ __forceinline__ void split2(float x, float y, unsigned& h, unsigned& l) {
    unsigned hp; asm("cvt.rn.bf16x2.f32 %0, %1, %2;" : "=r"(hp) : "f"(y), "f"(x));
    float hx = __uint_as_float(hp << 16);
    float hy = __uint_as_float(hp & 0xFFFF0000u);
    asm("cvt.rn.bf16x2.f32 %0, %1, %2;" : "=r"(l) : "f"(y - hy), "f"(x - hx));
    h = hp;
}
__device__ __forceinline__ void split8(float4 a, float4 b, uint4& h, uint4& l) {
    split2(a.x, a.y, h.x, l.x); split2(a.z, a.w, h.y, l.y);
    split2(b.x, b.y, h.z, l.z); split2(b.z, b.w, h.w, l.w);
}
__device__ __forceinline__ unsigned packhl(float v) {
    __nv_bfloat16 h = __float2bfloat16(v);
    float hf = __bfloat162float(h);
    __nv_bfloat16 lo = __float2bfloat16(v - hf);
    return ((unsigned)__bfloat16_as_ushort(h) << 16) | (unsigned)__bfloat16_as_ushort(lo);
}
// two packed words (elements k,k+1) -> bf16x2 hi pair / lo pair
__device__ __forceinline__ void unpack2(unsigned w0, unsigned w1, unsigned& h, unsigned& l) {
    h = (w1 & 0xFFFF0000u) | (w0 >> 16);
    l = (w1 << 16) | (w0 & 0xFFFFu);
}

// ---------------------------------------------------------------------------
// prep1 / prep2 / tr_invb / ablate : verified in earlier rounds
// ---------------------------------------------------------------------------
__global__ void prep1_k(const int* __restrict__ rraw, const int* __restrict__ araw,
                        const float* __restrict__ lambdas, const int* __restrict__ blen) {
    __shared__ int soff[RR];
    int t = threadIdx.x;
    bool r64 = (rraw[1] == 0);
    bool a64 = (araw[1] == 0);
    if (t < RR) g_ridx[t] = r64 ? rraw[2 * t] : rraw[t];
    if (t < AA) g_aidx[t] = a64 ? araw[2 * t] : araw[t];
    if (t == 0) {
        int acc = 0;
        for (int r = 0; r < RR; r++) { soff[r] = acc; acc += blen[r]; }
    }
    __syncthreads();
    for (int i = t; i < RK; i += 128) {
        int r = i >> 7, k = i & 127;
        g_lamk[i] = (k < blen[r]) ? lambdas[soff[r] + k] : 0.0f;
    }
}

__global__ void prep2_k(const float* __restrict__ bases, const float* __restrict__ means) {
    int gw = (blockIdx.x * blockDim.x + threadIdx.x) >> 5;
    int lane = threadIdx.x & 31;
    if (gw >= RK) return;
    int r = gw >> 7;
    const float4* b4 = (const float4*)(bases + (size_t)gw * DD);
    const float4* m4 = (const float4*)(means + (size_t)r * DD);
    float s = 0.f;
    #pragma unroll 3
    for (int j = lane; j < DD / 4; j += 32) {
        float4 bb = b4[j], mm = m4[j];
        s += bb.x * mm.x + bb.y * mm.y + bb.z * mm.z + bb.w * mm.w;
    }
    #pragma unroll
    for (int o = 16; o; o >>= 1) s += __shfl_xor_sync(0xffffffffu, s, o);
    if (lane == 0) g_lmb[gw] = g_lamk[gw] * s;
}

__global__ void tr_invb_k(const float* __restrict__ invb) {
    __shared__ float t[32][33];
    int rk0 = blockIdx.x << 5, d0 = blockIdx.y << 5;
    int r = threadIdx.x >> 3, c4 = (threadIdx.x & 7) << 2;
    float4 v = *(const float4*)(invb + (size_t)(rk0 + r) * DD + d0 + c4);
    t[r][c4] = v.x; t[r][c4 + 1] = v.y; t[r][c4 + 2] = v.z; t[r][c4 + 3] = v.w;
    __syncthreads();
    uint4 o;
    o.x = packhl(t[c4 + 0][r]); o.y = packhl(t[c4 + 1][r]);
    o.z = packhl(t[c4 + 2][r]); o.w = packhl(t[c4 + 3][r]);
    *(uint4*)(g_ivt + (size_t)(d0 + r) * RK + rk0 + c4) = o;
}

__global__ void ablate_k(const float* __restrict__ x, float* __restrict__ out) {
    __shared__ int sa[AA];
    if (threadIdx.x < AA) sa[threadIdx.x] = g_aidx[threadIdx.x];
    __syncthreads();
    int i = blockIdx.x * 256 + threadIdx.x;
    int n = i / (DD / 4), c = i % (DD / 4);
    const float4* x4 = (const float4*)x;
    float4 s = make_float4(0.f, 0.f, 0.f, 0.f);
    int base = n * SS;
    #pragma unroll 4
    for (int a = 0; a < AA; a++) {
        float4 v = x4[(size_t)(base + sa[a]) * (DD / 4) + c];
        s.x += v.x; s.y += v.y; s.z += v.z; s.w += v.w;
    }
    ((float4*)out)[i] = s;
}

// ---------------------------------------------------------------------------
// shared MMA compute over one K64 chunk (8 warps, 2x4 warp grid, 64x32/warp)
// acc[mf][j][4] += Ah*Bh + Ah*Bl + Al*Bh  on bf16 HMMA, fp32 accum
// ---------------------------------------------------------------------------
__device__ __forceinline__ void mma_chunk(uint32_t stg_addr, int wm, int wn, int lane,
                                          float acc[4][4][4]) {
    const int lr = lane & 15, lc8 = lane >> 4;
    #pragma unroll
    for (int ks = 0; ks < 4; ks++) {
        const uint32_t kb = (uint32_t)((ks * 16 + lc8 * 8) * 2);
        uint32_t ah[4][4], al[4][4];
        #pragma unroll
        for (int mf = 0; mf < 4; mf++) {
            uint32_t off = SWZ((uint32_t)((wm * 64 + mf * 16 + lr) * 128) + kb);
            ldsm4(ah[mf], stg_addr + off);
            ldsm4(al[mf], stg_addr + TILE_B + off);
        }
        uint32_t bh[2][4], bl[2][4];
        #pragma unroll
        for (int ng = 0; ng < 2; ng++) {
            uint32_t off = SWZ((uint32_t)((wn * 32 + ng * 16 + lr) * 128) + kb);
            ldsm4(bh[ng], stg_addr + 2 * TILE_B + off);
            ldsm4(bl[ng], stg_addr + 3 * TILE_B + off);
        }
        #pragma unroll
        for (int mf = 0; mf < 4; mf++) {
            #pragma unroll
            for (int j = 0; j < 4; j++) {
                const int ng = j >> 1, s = j & 1;
                mma16816(acc[mf][j], ah[mf], bh[ng][s], bh[ng][s + 2]);
                mma16816(acc[mf][j], ah[mf], bl[ng][s], bl[ng][s + 2]);
                mma16816(acc[mf][j], al[mf], bh[ng][s], bh[ng][s + 2]);
            }
        }
    }
}

// ---------------------------------------------------------------------------
// gemm1_mm: per (n-tile, r): C(128x128) = Xr @ Br^T, epilogue lam*C - lmb,
// stored packed bf16 hi/lo to g_chl.
// ---------------------------------------------------------------------------
__global__ __launch_bounds__(256)
void gemm1_mm(const float* __restrict__ x, const float* __restrict__ bases) {
    extern __shared__ char sm[];
    const uint32_t sb = smem_u32(sm);
    const int tid = threadIdx.x, wid = tid >> 5, lane = tid & 31;
    const int r = blockIdx.y, n0 = blockIdx.x << 7;
    const int wm = wid & 1, wn = wid >> 1;

    if (tid < KK) {
        ((float*)(sm + SM_LAM))[tid] = g_lamk[(r << 7) + tid];
        ((float*)(sm + SM_LMB))[tid] = g_lmb[(r << 7) + tid];
    }

    const int row = tid >> 1, half = tid & 1;
    const float* Arow = x + ((size_t)(n0 + row) * SS + g_ridx[r]) * DD;
    const float* Brow = bases + ((size_t)r * KK + row) * DD;

    float acc[4][4][4];
    #pragma unroll
    for (int a = 0; a < 4; a++)
        #pragma unroll
        for (int b = 0; b < 4; b++)
            #pragma unroll
            for (int c = 0; c < 4; c++) acc[a][b][c] = 0.f;

    // preload chunk 0
    {
        const uint32_t stg = SM_TILES;
        #pragma unroll
        for (int g = 0; g < 4; g++) {
            const int gcol = half * 32 + g * 8;
            const uint32_t off = SWZ((uint32_t)(row * 128 + gcol * 2));
            float4 a0 = *(const float4*)(Arow + gcol);
            float4 a1 = *(const float4*)(Arow + gcol + 4);
            uint4 h, l; split8(a0, a1, h, l);
            *(uint4*)(sm + stg + off) = h;
            *(uint4*)(sm + stg + TILE_B + off) = l;
            float4 b0 = *(const float4*)(Brow + gcol);
            float4 b1 = *(const float4*)(Brow + gcol + 4);
            split8(b0, b1, h, l);
            *(uint4*)(sm + stg + 2 * TILE_B + off) = h;
            *(uint4*)(sm + stg + 3 * TILE_B + off) = l;
        }
    }
    __syncthreads();

    for (int c = 0; c < DD / KCH; c++) {
        const int buf = c & 1;
        float4 ra[8], rb[8];
        if (c < DD / KCH - 1) {
            const int d0 = (c + 1) * KCH;
            #pragma unroll
            for (int g = 0; g < 4; g++) {
                const int gcol = half * 32 + g * 8;
                ra[2 * g]     = *(const float4*)(Arow + d0 + gcol);
                ra[2 * g + 1] = *(const float4*)(Arow + d0 + gcol + 4);
                rb[2 * g]     = *(const float4*)(Brow + d0 + gcol);
                rb[2 * g + 1] = *(const float4*)(Brow + d0 + gcol + 4);
            }
        }
        mma_chunk(sb + SM_TILES + buf * STAGE_B, wm, wn, lane, acc);
        if (c < DD / KCH - 1) {
            const uint32_t stg = SM_TILES + (buf ^ 1) * STAGE_B;
            #pragma unroll
            for (int g = 0; g < 4; g++) {
                const int gcol = half * 32 + g * 8;
                const uint32_t off = SWZ((uint32_t)(row * 128 + gcol * 2));
                uint4 h, l;
                split8(ra[2 * g], ra[2 * g + 1], h, l);
                *(uint4*)(sm + stg + off) = h;
                *(uint4*)(sm + stg + TILE_B + off) = l;
                split8(rb[2 * g], rb[2 * g + 1], h, l);
                *(uint4*)(sm + stg + 2 * TILE_B + off) = h;
                *(uint4*)(sm + stg + 3 * TILE_B + off) = l;
            }
        }
        __syncthreads();
    }

    const float* slam = (const float*)(sm + SM_LAM);
    const float* slmb = (const float*)(sm + SM_LMB);
    #pragma unroll
    for (int mf = 0; mf < 4; mf++) {
        const int grow = n0 + wm * 64 + mf * 16 + (lane >> 2);
        #pragma unroll
        for (int j = 0; j < 4; j++) {
            const int col = wn * 32 + j * 8 + 2 * (lane & 3);
            uint2 p;
            p.x = packhl(slam[col] * acc[mf][j][0] - slmb[col]);
            p.y = packhl(slam[col + 1] * acc[mf][j][1] - slmb[col + 1]);
            *(uint2*)(g_chl + (size_t)grow * RK + (r << 7) + col) = p;
            p.x = packhl(slam[col] * acc[mf][j][2] - slmb[col]);
            p.y = packhl(slam[col + 1] * acc[mf][j][3] - slmb[col + 1]);
            *(uint2*)(g_chl + (size_t)(grow + 8) * RK + (r << 7) + col) = p;
        }
    }
}

// ---------------------------------------------------------------------------
// gemm2_mm: per (n-tile, d-tile, z): part[z] = coeffs[:,kz] @ invbT[d,kz]^T
// A from g_chl (packed), B from g_ivt (packed).
// ---------------------------------------------------------------------------
__global__ __launch_bounds__(256)
void gemm2_mm() {
    extern __shared__ char sm[];
    const uint32_t sb = smem_u32(sm);
    const int tid = threadIdx.x, wid = tid >> 5, lane = tid & 31;
    const int n0 = blockIdx.x << 7, d0 = blockIdx.y << 7, z = blockIdx.z;
    const int wm = wid & 1, wn = wid >> 1;

    const int row = tid >> 1, half = tid & 1;
    const unsigned* Arow = g_chl + (size_t)(n0 + row) * RK + (size_t)z * KSPLIT;
    const unsigned* Brow = g_ivt + (size_t)(d0 + row) * RK + (size_t)z * KSPLIT;

    float acc[4][4][4];
    #pragma unroll
    for (int a = 0; a < 4; a++)
        #pragma unroll
        for (int b = 0; b < 4; b++)
            #pragma unroll
            for (int c = 0; c < 4; c++) acc[a][b][c] = 0.f;

    // preload chunk 0
    {
        const uint32_t stg = SM_TILES;
        #pragma unroll
        for (int g = 0; g < 4; g++) {
            const int gcol = half * 32 + g * 8;
            const uint32_t off = SWZ((uint32_t)(row * 128 + gcol * 2));
            uint4 w0 = *(const uint4*)(Arow + gcol);
            uint4 w1 = *(const uint4*)(Arow + gcol + 4);
            uint4 h, l;
            unpack2(w0.x, w0.y, h.x, l.x); unpack2(w0.z, w0.w, h.y, l.y);
            unpack2(w1.x, w1.y, h.z, l.z); unpack2(w1.z, w1.w, h.w, l.w);
            *(uint4*)(sm + stg + off) = h;
            *(uint4*)(sm + stg + TILE_B + off) = l;
            w0 = *(const uint4*)(Brow + gcol);
            w1 = *(const uint4*)(Brow + gcol + 4);
            unpack2(w0.x, w0.y, h.x, l.x); unpack2(w0.z, w0.w, h.y, l.y);
            unpack2(w1.x, w1.y, h.z, l.z); unpack2(w1.z, w1.w, h.w, l.w);
            *(uint4*)(sm + stg + 2 * TILE_B + off) = h;
            *(uint4*)(sm + stg + 3 * TILE_B + off) = l;
        }
    }
    __syncthreads();

    for (int c = 0; c < KSPLIT / KCH; c++) {
        const int buf = c & 1;
        uint4 ra[4], ra1[4], rb[4], rb1[4];
        if (c < KSPLIT / KCH - 1) {
            const int k0 = (c + 1) * KCH;
            #pragma unroll
            for (int g = 0; g < 4; g++) {
                const int gcol = half * 32 + g * 8;
                ra[g]  = *(const uint4*)(Arow + k0 + gcol);
                ra1[g] = *(const uint4*)(Arow + k0 + gcol + 4);
                rb[g]  = *(const uint4*)(Brow + k0 + gcol);
                rb1[g] = *(const uint4*)(Brow + k0 + gcol + 4);
            }
        }
        mma_chunk(sb + SM_TILES + buf * STAGE_B, wm, wn, lane, acc);
        if (c < KSPLIT / KCH - 1) {
            const uint32_t stg = SM_TILES + (buf ^ 1) * STAGE_B;
            #pragma unroll
            for (int g = 0; g < 4; g++) {
                const int gcol = half * 32 + g * 8;
                const uint32_t off = SWZ((uint32_t)(row * 128 + gcol * 2));
                uint4 h, l;
                unpack2(ra[g].x, ra[g].y, h.x, l.x); unpack2(ra[g].z, ra[g].w, h.y, l.y);
                unpack2(ra1[g].x, ra1[g].y, h.z, l.z); unpack2(ra1[g].z, ra1[g].w, h.w, l.w);
                *(uint4*)(sm + stg + off) = h;
                *(uint4*)(sm + stg + TILE_B + off) = l;
                unpack2(rb[g].x, rb[g].y, h.x, l.x); unpack2(rb[g].z, rb[g].w, h.y, l.y);
                unpack2(rb1[g].x, rb1[g].y, h.z, l.z); unpack2(rb1[g].z, rb1[g].w, h.w, l.w);
                *(uint4*)(sm + stg + 2 * TILE_B + off) = h;
                *(uint4*)(sm + stg + 3 * TILE_B + off) = l;
            }
        }
        __syncthreads();
    }

    float* P = g_part + (size_t)z * (NN * DD);
    #pragma unroll
    for (int mf = 0; mf < 4; mf++) {
        const int grow = n0 + wm * 64 + mf * 16 + (lane >> 2);
        #pragma unroll
        for (int j = 0; j < 4; j++) {
            const int col = d0 + wn * 32 + j * 8 + 2 * (lane & 3);
            *(float2*)(P + (size_t)grow * DD + col) = make_float2(acc[mf][j][0], acc[mf][j][1]);
            *(float2*)(P + (size_t)(grow + 8) * DD + col) = make_float2(acc[mf][j][2], acc[mf][j][3]);
        }
    }
}

// ---------------------------------------------------------------------------
// reduce_k: out += sum_z part[z]
// ---------------------------------------------------------------------------
__global__ void reduce_k(float* __restrict__ out) {
    int i = blockIdx.x * 256 + threadIdx.x;
    float4 s = ((const float4*)out)[i];
    const float4* p4 = (const float4*)g_part;
    #pragma unroll
    for (int zz = 0; zz < SPLITK; zz++) {
        float4 v = p4[(size_t)zz * (NN * DD / 4) + i];
        s.x += v.x; s.y += v.y; s.z += v.z; s.w += v.w;
    }
    ((float4*)out)[i] = s;
}

// ---------------------------------------------------------------------------
extern "C" void kernel_launch(void* const* d_in, const int* in_sizes, int n_in,
                              void* d_out, int out_size) {
    (void)in_sizes; (void)n_in; (void)out_size;
    const float* x       = (const float*)d_in[0];
    const float* lambdas = (const float*)d_in[1];
    const float* bases   = (const float*)d_in[2];
    const float* invb    = (const float*)d_in[3];
    const float* means   = (const float*)d_in[4];
    const int*   rraw    = (const int*)d_in[5];
    const int*   araw    = (const int*)d_in[6];
    const int*   blen    = (const int*)d_in[7];
    float* out = (float*)d_out;

    cudaFuncSetAttribute(gemm1_mm, cudaFuncAttributeMaxDynamicSharedMemorySize, SMEMSZ);
    cudaFuncSetAttribute(gemm2_mm, cudaFuncAttributeMaxDynamicSharedMemorySize, SMEMSZ);

    prep1_k<<<1, 128>>>(rraw, araw, lambdas, blen);
    prep2_k<<<1536, 256>>>(bases, means);
    tr_invb_k<<<dim3(RK / 32, DD / 32), 256>>>(invb);
    ablate_k<<<768, 256>>>(x, out);
    gemm1_mm<<<dim3(8, RR), 256, SMEMSZ>>>(x, bases);
    gemm2_mm<<<dim3(8, DD / 128, SPLITK), 256, SMEMSZ>>>();
    reduce_k<<<768, 256>>>(out);
}